// round 11
// baseline (speedup 1.0000x reference)
#include <cuda_runtime.h>
#include <math.h>

#define BS 4096
#define NV 778
#define KPAD 152                     // K padded to 19*8
#define MROWS 2334                   // NV*3
#define MP 2432                      // M padded to 19*128
#define VOUT_ELEMS (BS * NV * 3)
#define VT 64                        // vertices per lbs block
#define BT 32                        // batches per lbs block
#define NVP 832                      // NV padded to 13*64
#define SOS 97                       // s_out row stride

#define NB_DIRS ((KPAD * MP) / 256)          // 1444
#define NB_W    ((16 * NVP) / 256)           // 52
#define NB_POSE ((45 * BS) / 256)            // 720
#define NB_JREG 48

typedef unsigned long long ull;
union U2 { ulonglong2 v; ull p[2]; };
union F4 { float4 v; float a[4]; };
union P2 { float2 f; ull u; };

__device__ __forceinline__ ull fma2(ull a, ull b, ull c) {
    ull d;
    asm("fma.rn.f32x2 %0, %1, %2, %3;" : "=l"(d) : "l"(a), "l"(b), "l"(c));
    return d;
}
__device__ __forceinline__ ull add2(ull a, ull b) {
    ull d;
    asm("add.rn.f32x2 %0, %1, %2;" : "=l"(d) : "l"(a), "l"(b));
    return d;
}
__device__ __forceinline__ ull pack2(float x, float y) {
    ull d;
    asm("mov.b64 %0, {%1, %2};" : "=l"(d) : "f"(x), "f"(y));
    return d;
}
__device__ __forceinline__ void unpack2(ull p, float& x, float& y) {
    asm("mov.b64 {%0, %1}, %2;" : "=f"(x), "=f"(y) : "l"(p));
}

// ---------------- scratch ----------------
__device__ __align__(16) float g_dirsT[KPAD * MP];    // [k][m]
__device__ __align__(16) float g_featT[KPAD * BS];    // [k][b]
__device__ __align__(16) float g_poseT[45 * BS];      // [c][b]
__device__ __align__(16) float g_h[MROWS * BS];       // [vd][b]
__device__ __align__(16) float g_se3T[192 * BS];      // [e][b]
__device__ __align__(16) float g_off[3 * BS];         // [d][b]
__device__ __align__(16) float g_wT[16 * NVP];        // [j][v]
__device__ float g_JS[16 * 3 * 10];
__device__ float g_JT[16 * 3];

__constant__ int c_parent[16]   = {-1,0,1,2,0,4,5,0,7,8,0,10,11,0,13,14};
__constant__ int c_src2pos[16]  = {0,5,6,7,9,10,11,17,18,19,13,14,15,1,2,3};

// ---------------- kernel 0: merged preprocessing (dirsT | wT | poseT | jreg) ----------------
__global__ void __launch_bounds__(256) k_pre(const float* __restrict__ posedirs,
                                             const float* __restrict__ shapedirs,
                                             const float* __restrict__ weights,
                                             const float* __restrict__ pose,
                                             const float* __restrict__ Jreg,
                                             const float* __restrict__ v_template) {
    __shared__ float red[256][11];
    int jb = blockIdx.x;
    int tid = threadIdx.x;

    if (jb < NB_DIRS) {
        int idx = jb * 256 + tid;
        int m = idx % MP;
        int k = idx / MP;
        float val = 0.0f;
        if (m < MROWS) {
            if (k < 135)      val = posedirs[m * 135 + k];
            else if (k < 145) val = shapedirs[m * 10 + (k - 135)];
        }
        g_dirsT[idx] = val;
        return;
    }
    jb -= NB_DIRS;
    if (jb < NB_W) {
        int idx = jb * 256 + tid;
        int v = idx % NVP;
        int j = idx / NVP;
        g_wT[idx] = (v < NV) ? weights[v * 16 + j] : 0.0f;
        return;
    }
    jb -= NB_W;
    if (jb < NB_POSE) {
        int idx = jb * 256 + tid;
        int b = idx % BS;
        int c = idx / BS;
        g_poseT[idx] = pose[b * 45 + c];
        return;
    }
    jb -= NB_POSE;
    {
        int jd = jb;                 // 0..47
        int j = jd / 3, d = jd % 3;
        float acc[11];
#pragma unroll
        for (int i = 0; i < 11; i++) acc[i] = 0.0f;
        for (int v = tid; v < NV; v += 256) {
            float r = Jreg[j * NV + v];
            const float* sd = shapedirs + (v * 3 + d) * 10;
#pragma unroll
            for (int s = 0; s < 10; s++) acc[s] = fmaf(r, sd[s], acc[s]);
            acc[10] = fmaf(r, v_template[v * 3 + d], acc[10]);
        }
#pragma unroll
        for (int i = 0; i < 11; i++) red[tid][i] = acc[i];
        __syncthreads();
        for (int off = 128; off > 0; off >>= 1) {
            if (tid < off) {
#pragma unroll
                for (int i = 0; i < 11; i++) red[tid][i] += red[tid + off][i];
            }
            __syncthreads();
        }
        if (tid == 0) {
#pragma unroll
            for (int s = 0; s < 10; s++) g_JS[jd * 10 + s] = red[0][s];
            g_JT[jd] = red[0][10];
        }
    }
}

// ---------------- kernel 1a: per-(batch,joint) Rodrigues ----------------
__global__ void __launch_bounds__(256) k_rot(const float* __restrict__ hc,
                                             const float* __restrict__ hm) {
    int b  = blockIdx.x * 256 + threadIdx.x;
    int jj = blockIdx.y;   // 0..14

    float ax = hm[3 * jj], ay = hm[3 * jj + 1], az = hm[3 * jj + 2];
    for (int c = 0; c < 45; c++) {
        float p = g_poseT[c * BS + b];
        const float* h = hc + c * 45 + 3 * jj;
        ax = fmaf(p, h[0], ax);
        ay = fmaf(p, h[1], ay);
        az = fmaf(p, h[2], az);
    }
    float a2  = ax * ax + ay * ay + az * az + 1e-12f;
    float ang = sqrtf(a2);
    float inv = 1.0f / ang;
    float ux = ax * inv, uy = ay * inv, uz = az * inv;
    float cc = cosf(ang), ss = sinf(ang), oc = 1.0f - cc;
    float R00 = cc + oc * ux * ux;
    float R01 = -ss * uz + oc * ux * uy;
    float R02 =  ss * uy + oc * ux * uz;
    float R10 =  ss * uz + oc * ux * uy;
    float R11 = cc + oc * uy * uy;
    float R12 = -ss * ux + oc * uy * uz;
    float R20 = -ss * uy + oc * ux * uz;
    float R21 =  ss * ux + oc * uy * uz;
    float R22 = cc + oc * uz * uz;

    g_featT[(9*jj+0)*BS + b] = R00 - 1.0f;
    g_featT[(9*jj+1)*BS + b] = R01;
    g_featT[(9*jj+2)*BS + b] = R02;
    g_featT[(9*jj+3)*BS + b] = R10;
    g_featT[(9*jj+4)*BS + b] = R11 - 1.0f;
    g_featT[(9*jj+5)*BS + b] = R12;
    g_featT[(9*jj+6)*BS + b] = R20;
    g_featT[(9*jj+7)*BS + b] = R21;
    g_featT[(9*jj+8)*BS + b] = R22 - 1.0f;
}

// ---------------- kernel 1b: per-(batch,row) SE3 chain ----------------
__global__ void __launch_bounds__(128) k_chain(const float* __restrict__ root_rotation,
                                               const float* __restrict__ shape,
                                               const float* __restrict__ trans,
                                               float* __restrict__ jout) {
    int b = blockIdx.x * 128 + threadIdx.x;
    int r = blockIdx.y;   // 0..2

    float sh[10];
#pragma unroll
    for (int s = 0; s < 10; s++) sh[s] = shape[b * 10 + s];
    if (r == 0) {
#pragma unroll
        for (int s = 0; s < 10; s++) g_featT[(135 + s) * BS + b] = sh[s];
#pragma unroll
        for (int z = 145; z < KPAD; z++) g_featT[z * BS + b] = 0.0f;
    }

    float jt0[3];
#pragma unroll
    for (int d = 0; d < 3; d++) {
        float a = g_JT[d];
        const float* js = g_JS + d * 10;
#pragma unroll
        for (int s = 0; s < 10; s++) a = fmaf(js[s], sh[s], a);
        jt0[d] = a;
    }

    float A[16][4];
    {
        float R0 = root_rotation[b * 9 + r * 3 + 0];
        float R1 = root_rotation[b * 9 + r * 3 + 1];
        float R2 = root_rotation[b * 9 + r * 3 + 2];
        A[0][0] = R0; A[0][1] = R1; A[0][2] = R2;
        A[0][3] = jt0[r] - (R0 * jt0[0] + R1 * jt0[1] + R2 * jt0[2]);
    }

    float center = jt0[r];
    float off = trans[b * 3 + r] - center;
    g_off[r * BS + b] = off;

#pragma unroll
    for (int c = 0; c < 4; c++) g_se3T[(0 * 12 + r * 4 + c) * BS + b] = A[0][c];
    jout[((size_t)b * 21 + 0) * 3 + r] = center + off;

#pragma unroll
    for (int i = 1; i < 16; i++) {
        int p = c_parent[i];
        float jx, jy, jz;
        {
            float a0 = g_JT[i * 3 + 0], a1 = g_JT[i * 3 + 1], a2 = g_JT[i * 3 + 2];
            const float* js0 = g_JS + (i * 3 + 0) * 10;
            const float* js1 = g_JS + (i * 3 + 1) * 10;
            const float* js2 = g_JS + (i * 3 + 2) * 10;
#pragma unroll
            for (int s = 0; s < 10; s++) {
                a0 = fmaf(js0[s], sh[s], a0);
                a1 = fmaf(js1[s], sh[s], a1);
                a2 = fmaf(js2[s], sh[s], a2);
            }
            jx = a0; jy = a1; jz = a2;
        }
        float R[9];
#pragma unroll
        for (int e = 0; e < 9; e++) R[e] = g_featT[(9 * (i - 1) + e) * BS + b];
        R[0] += 1.0f; R[4] += 1.0f; R[8] += 1.0f;

        float t0 = jx - (R[0]*jx + R[1]*jy + R[2]*jz);
        float t1 = jy - (R[3]*jx + R[4]*jy + R[5]*jz);
        float t2 = jz - (R[6]*jx + R[7]*jy + R[8]*jz);

        float p0 = A[p][0], p1 = A[p][1], p2 = A[p][2], p3 = A[p][3];
        A[i][0] = p0*R[0] + p1*R[3] + p2*R[6];
        A[i][1] = p0*R[1] + p1*R[4] + p2*R[7];
        A[i][2] = p0*R[2] + p1*R[5] + p2*R[8];
        A[i][3] = p0*t0 + p1*t1 + p2*t2 + p3;

#pragma unroll
        for (int c = 0; c < 4; c++) g_se3T[(i * 12 + r * 4 + c) * BS + b] = A[i][c];

        float jl = p0*jx + p1*jy + p2*jz + p3;
        jout[((size_t)b * 21 + c_src2pos[i]) * 3 + r] = jl + off;
    }
}

// ---------------- kernel 2: tiled SGEMM (FFMA2): M128 x N64, 8m x 4b micro ----------------
__global__ void __launch_bounds__(256, 3) k_gemm(const float* __restrict__ v_template) {
    __shared__ float As[2][8][256];   // m duplicated pairs
    __shared__ float Bs[2][8][64];

    int tid = threadIdx.x;
    int bblk = blockIdx.x * 64;
    int mblk = blockIdx.y * 128;
    int lk  = tid >> 5;           // 0..7 (A load row)
    int l4  = (tid & 31) * 4;     // 0..124
    int lkb = tid >> 4;           // 0..7 for tid<128 (B load row)
    int l4b = (tid & 15) * 4;     // 0..60

    int tx = tid & 15;            // n-group (4 batches)
    int ty = tid >> 4;            // m-group (8 rows)

    ull c[8][2];
#pragma unroll
    for (int m = 0; m < 8; m++) { c[m][0] = 0ULL; c[m][1] = 0ULL; }

    F4 a4, b4;
    a4.v = *reinterpret_cast<const float4*>(g_dirsT + lk * MP + mblk + l4);
    if (tid < 128)
        b4.v = *reinterpret_cast<const float4*>(g_featT + lkb * BS + bblk + l4b);
    {
        float4 d0 = make_float4(a4.a[0], a4.a[0], a4.a[1], a4.a[1]);
        float4 d1 = make_float4(a4.a[2], a4.a[2], a4.a[3], a4.a[3]);
        *reinterpret_cast<float4*>(&As[0][lk][2 * l4])     = d0;
        *reinterpret_cast<float4*>(&As[0][lk][2 * l4 + 4]) = d1;
        if (tid < 128)
            *reinterpret_cast<float4*>(&Bs[0][lkb][l4b]) = b4.v;
    }
    __syncthreads();

    for (int s = 0; s < 19; s++) {
        int cur = s & 1;
        bool hasNext = (s + 1 < 19);
        if (hasNext) {
            a4.v = *reinterpret_cast<const float4*>(g_dirsT + ((s+1)*8 + lk) * MP + mblk + l4);
            if (tid < 128)
                b4.v = *reinterpret_cast<const float4*>(g_featT + ((s+1)*8 + lkb) * BS + bblk + l4b);
        }
#pragma unroll
        for (int k = 0; k < 8; k++) {
            U2 a01, a23, a45, a67;
            a01.v = *reinterpret_cast<const ulonglong2*>(&As[cur][k][8 * ty]);
            a23.v = *reinterpret_cast<const ulonglong2*>(&As[cur][k][8 * ty + 4]);
            a45.v = *reinterpret_cast<const ulonglong2*>(&As[cur][k][128 + 8 * ty]);
            a67.v = *reinterpret_cast<const ulonglong2*>(&As[cur][k][128 + 8 * ty + 4]);
            U2 b01;
            b01.v = *reinterpret_cast<const ulonglong2*>(&Bs[cur][k][4 * tx]);
            ull am[8] = {a01.p[0], a01.p[1], a23.p[0], a23.p[1],
                         a45.p[0], a45.p[1], a67.p[0], a67.p[1]};
#pragma unroll
            for (int m = 0; m < 8; m++) {
                c[m][0] = fma2(am[m], b01.p[0], c[m][0]);
                c[m][1] = fma2(am[m], b01.p[1], c[m][1]);
            }
        }
        if (hasNext) {
            int nxt = 1 - cur;
            float4 d0 = make_float4(a4.a[0], a4.a[0], a4.a[1], a4.a[1]);
            float4 d1 = make_float4(a4.a[2], a4.a[2], a4.a[3], a4.a[3]);
            *reinterpret_cast<float4*>(&As[nxt][lk][2 * l4])     = d0;
            *reinterpret_cast<float4*>(&As[nxt][lk][2 * l4 + 4]) = d1;
            if (tid < 128)
                *reinterpret_cast<float4*>(&Bs[nxt][lkb][l4b]) = b4.v;
        }
        __syncthreads();
    }

#pragma unroll
    for (int m = 0; m < 8; m++) {
        int m_local = (m < 4) ? (4 * ty + m) : (64 + 4 * ty + (m - 4));
        int mg = mblk + m_local;
        if (mg >= MROWS) continue;
        float vt = v_template[mg];
        F4 o0;
        unpack2(c[m][0], o0.a[0], o0.a[1]);
        unpack2(c[m][1], o0.a[2], o0.a[3]);
#pragma unroll
        for (int i = 0; i < 4; i++) o0.a[i] += vt;
        *reinterpret_cast<float4*>(g_h + (size_t)mg * BS + bblk + 4 * tx) = o0.v;
    }
}

// ---------------- kernel 3: LBS blend — smem-staged SE3, 4 v x 1 b-pair / thread ----------------
__global__ void __launch_bounds__(256, 2) k_lbs(float* __restrict__ out) {
    __shared__ float sA[VT * SOS];
    __shared__ float sW[16 * VT];

    int tid = threadIdx.x;
    int bx  = tid & 15;
    int vg  = tid >> 4;
    int vblk = blockIdx.x * VT;
    int bblk = blockIdx.y * BT;
    int b0 = bblk + bx * 2;
    int v0 = vblk + vg * 4;

    // A tile [192][BT] = 1536 float4
#pragma unroll
    for (int t = tid; t < 192 * (BT / 4); t += 256) {
        int e = t >> 3;
        int q = (t & 7) * 4;
        *reinterpret_cast<float4*>(&sA[e * BT + q]) =
            *reinterpret_cast<const float4*>(g_se3T + (size_t)e * BS + bblk + q);
    }
    {
        int t = tid;
        int j = t >> 4, q = t & 15;
        *reinterpret_cast<float4*>(&sW[j * VT + q * 4]) =
            *reinterpret_cast<const float4*>(g_wT + j * NVP + vblk + q * 4);
    }

    ull h[4][3];
#pragma unroll
    for (int u = 0; u < 4; u++) {
        int vv = v0 + u;
        if (vv > NV - 1) vv = NV - 1;
#pragma unroll
        for (int d = 0; d < 3; d++) {
            P2 t;
            t.f = *reinterpret_cast<const float2*>(g_h + (size_t)(vv * 3 + d) * BS + b0);
            h[u][d] = t.u;
        }
    }

    __syncthreads();

    ull acc[4][3];
#pragma unroll
    for (int u = 0; u < 4; u++)
#pragma unroll
        for (int r = 0; r < 3; r++) acc[u][r] = 0ULL;

#pragma unroll
    for (int j = 0; j < 16; j++) {
        F4 w4;
        w4.v = *reinterpret_cast<const float4*>(&sW[j * VT + vg * 4]);
        ull A[12];
#pragma unroll
        for (int e = 0; e < 12; e++)
            A[e] = *reinterpret_cast<const ull*>(&sA[(j * 12 + e) * BT + bx * 2]);
#pragma unroll
        for (int u = 0; u < 4; u++) {
            ull wp = pack2(w4.a[u], w4.a[u]);
#pragma unroll
            for (int r = 0; r < 3; r++) {
                ull t = fma2(A[r*4+0], h[u][0],
                        fma2(A[r*4+1], h[u][1],
                        fma2(A[r*4+2], h[u][2], A[r*4+3])));
                acc[u][r] = fma2(wp, t, acc[u][r]);
            }
        }
    }

    ull offp[3];
#pragma unroll
    for (int d = 0; d < 3; d++) {
        P2 t;
        t.f = *reinterpret_cast<const float2*>(g_off + d * BS + b0);
        offp[d] = t.u;
    }

    __syncthreads();
    float* s_out = sA;

#pragma unroll
    for (int u = 0; u < 4; u++) {
        int v = v0 + u;
        bool val = (v < NV);
        int pos = -1;
        if      (v == 745) pos = 4;
        else if (v == 333) pos = 8;
        else if (v == 444) pos = 12;
        else if (v == 555) pos = 16;
        else if (v == 672) pos = 20;
        float o[3][2];
#pragma unroll
        for (int r = 0; r < 3; r++) {
            ull s = add2(acc[u][r], offp[r]);
            unpack2(s, o[r][0], o[r][1]);
        }
        int vl = vg * 4 + u;
#pragma unroll
        for (int i = 0; i < 2; i++) {
            int bl = bx * 2 + i;
            if (val) {
                s_out[vl * SOS + bl * 3 + 0] = o[0][i];
                s_out[vl * SOS + bl * 3 + 1] = o[1][i];
                s_out[vl * SOS + bl * 3 + 2] = o[2][i];
            }
            if (pos >= 0) {
                int b = b0 + i;
                float* jo = out + (size_t)VOUT_ELEMS + ((size_t)b * 21 + pos) * 3;
                jo[0] = o[0][i]; jo[1] = o[1][i]; jo[2] = o[2][i];
            }
        }
    }

    __syncthreads();

    int nv_here = NV - vblk;
    if (nv_here > VT) nv_here = VT;
    int row_floats = nv_here * 3;
#pragma unroll 4
    for (int t = tid; t < BT * (VT * 3); t += 256) {
        int bl = t / (VT * 3);
        int e  = t % (VT * 3);
        if (e < row_floats) {
            int vl = e / 3;
            int d  = e - vl * 3;
            out[((size_t)(bblk + bl) * NV + vblk) * 3 + e] =
                s_out[vl * SOS + bl * 3 + d];
        }
    }
}

// ---------------- launch ----------------
extern "C" void kernel_launch(void* const* d_in, const int* in_sizes, int n_in,
                              void* d_out, int out_size) {
    const float* root_rotation = (const float*)d_in[0];
    const float* pose          = (const float*)d_in[1];
    const float* shape         = (const float*)d_in[2];
    const float* trans         = (const float*)d_in[3];
    const float* hc            = (const float*)d_in[4];
    const float* hm            = (const float*)d_in[5];
    const float* shapedirs     = (const float*)d_in[6];
    const float* posedirs      = (const float*)d_in[7];
    const float* v_template    = (const float*)d_in[8];
    const float* Jreg          = (const float*)d_in[9];
    const float* weights       = (const float*)d_in[10];
    float* out = (float*)d_out;

    k_pre<<<NB_DIRS + NB_W + NB_POSE + NB_JREG, 256>>>(posedirs, shapedirs, weights,
                                                       pose, Jreg, v_template);

    dim3 rgrid(BS / 256, 15);
    k_rot<<<rgrid, 256>>>(hc, hm);
    dim3 cgrid(BS / 128, 3);
    k_chain<<<cgrid, 128>>>(root_rotation, shape, trans, out + VOUT_ELEMS);

    dim3 ggrid(BS / 64, 19);
    k_gemm<<<ggrid, 256>>>(v_template);
    dim3 lgrid((NV + VT - 1) / VT, BS / BT);
    k_lbs<<<lgrid, 256>>>(out);
}

// round 12
// speedup vs baseline: 1.1416x; 1.1416x over previous
#include <cuda_runtime.h>
#include <math.h>

#define BS 4096
#define NV 778
#define KPAD 152                     // K padded to 19*8
#define MROWS 2334                   // NV*3
#define MP 2432                      // M padded to 19*128
#define VOUT_ELEMS (BS * NV * 3)
#define VT 64                        // vertices per lbs block
#define BT 32                        // batches per lbs block
#define NVP 832                      // NV padded to 13*64
#define SOS 97                       // s_out row stride

#define NB_DIRS ((KPAD * MP) / 256)          // 1444
#define NB_W    ((16 * NVP) / 256)           // 52
#define NB_POSE ((45 * BS) / 256)            // 720
#define NB_JREG 48

typedef unsigned long long ull;
union U2 { ulonglong2 v; ull p[2]; };
union F4 { float4 v; float a[4]; };
union P2 { float2 f; ull u; };

__device__ __forceinline__ ull fma2(ull a, ull b, ull c) {
    ull d;
    asm("fma.rn.f32x2 %0, %1, %2, %3;" : "=l"(d) : "l"(a), "l"(b), "l"(c));
    return d;
}
__device__ __forceinline__ ull add2(ull a, ull b) {
    ull d;
    asm("add.rn.f32x2 %0, %1, %2;" : "=l"(d) : "l"(a), "l"(b));
    return d;
}
__device__ __forceinline__ ull pack2(float x, float y) {
    ull d;
    asm("mov.b64 %0, {%1, %2};" : "=l"(d) : "f"(x), "f"(y));
    return d;
}
__device__ __forceinline__ void unpack2(ull p, float& x, float& y) {
    asm("mov.b64 {%0, %1}, %2;" : "=f"(x), "=f"(y) : "l"(p));
}

// ---------------- scratch ----------------
__device__ __align__(16) float g_dirsT[KPAD * MP];    // [k][m]
__device__ __align__(16) float g_featT[KPAD * BS];    // [k][b]
__device__ __align__(16) float g_poseT[45 * BS];      // [c][b]
__device__ __align__(16) float g_h[MROWS * BS];       // [vd][b]
__device__ __align__(16) float g_se3T[192 * BS];      // [e][b]
__device__ __align__(16) float g_off[3 * BS];         // [d][b]
__device__ __align__(16) float g_wT[16 * NVP];        // [j][v]
__device__ float g_JS[16 * 3 * 10];
__device__ float g_JT[16 * 3];

__constant__ int c_parent[16]   = {-1,0,1,2,0,4,5,0,7,8,0,10,11,0,13,14};
__constant__ int c_src2pos[16]  = {0,5,6,7,9,10,11,17,18,19,13,14,15,1,2,3};

// ---------------- kernel 0: merged preprocessing (dirsT | wT | poseT | jreg) ----------------
__global__ void __launch_bounds__(256) k_pre(const float* __restrict__ posedirs,
                                             const float* __restrict__ shapedirs,
                                             const float* __restrict__ weights,
                                             const float* __restrict__ pose,
                                             const float* __restrict__ Jreg,
                                             const float* __restrict__ v_template) {
    __shared__ float red[256][11];
    int jb = blockIdx.x;
    int tid = threadIdx.x;

    if (jb < NB_DIRS) {
        int idx = jb * 256 + tid;
        int m = idx % MP;
        int k = idx / MP;
        float val = 0.0f;
        if (m < MROWS) {
            if (k < 135)      val = posedirs[m * 135 + k];
            else if (k < 145) val = shapedirs[m * 10 + (k - 135)];
        }
        g_dirsT[idx] = val;
        return;
    }
    jb -= NB_DIRS;
    if (jb < NB_W) {
        int idx = jb * 256 + tid;
        int v = idx % NVP;
        int j = idx / NVP;
        g_wT[idx] = (v < NV) ? weights[v * 16 + j] : 0.0f;
        return;
    }
    jb -= NB_W;
    if (jb < NB_POSE) {
        int idx = jb * 256 + tid;
        int b = idx % BS;
        int c = idx / BS;
        g_poseT[idx] = pose[b * 45 + c];
        return;
    }
    jb -= NB_POSE;
    {
        int jd = jb;                 // 0..47
        int j = jd / 3, d = jd % 3;
        float acc[11];
#pragma unroll
        for (int i = 0; i < 11; i++) acc[i] = 0.0f;
        for (int v = tid; v < NV; v += 256) {
            float r = Jreg[j * NV + v];
            const float* sd = shapedirs + (v * 3 + d) * 10;
#pragma unroll
            for (int s = 0; s < 10; s++) acc[s] = fmaf(r, sd[s], acc[s]);
            acc[10] = fmaf(r, v_template[v * 3 + d], acc[10]);
        }
#pragma unroll
        for (int i = 0; i < 11; i++) red[tid][i] = acc[i];
        __syncthreads();
        for (int off = 128; off > 0; off >>= 1) {
            if (tid < off) {
#pragma unroll
                for (int i = 0; i < 11; i++) red[tid][i] += red[tid + off][i];
            }
            __syncthreads();
        }
        if (tid == 0) {
#pragma unroll
            for (int s = 0; s < 10; s++) g_JS[jd * 10 + s] = red[0][s];
            g_JT[jd] = red[0][10];
        }
    }
}

// ---------------- kernel 1a: per-(batch,joint) Rodrigues ----------------
__global__ void __launch_bounds__(256) k_rot(const float* __restrict__ hc,
                                             const float* __restrict__ hm) {
    int b  = blockIdx.x * 256 + threadIdx.x;
    int jj = blockIdx.y;   // 0..14

    float ax = hm[3 * jj], ay = hm[3 * jj + 1], az = hm[3 * jj + 2];
    for (int c = 0; c < 45; c++) {
        float p = g_poseT[c * BS + b];
        const float* h = hc + c * 45 + 3 * jj;
        ax = fmaf(p, h[0], ax);
        ay = fmaf(p, h[1], ay);
        az = fmaf(p, h[2], az);
    }
    float a2  = ax * ax + ay * ay + az * az + 1e-12f;
    float ang = sqrtf(a2);
    float inv = 1.0f / ang;
    float ux = ax * inv, uy = ay * inv, uz = az * inv;
    float cc = cosf(ang), ss = sinf(ang), oc = 1.0f - cc;
    float R00 = cc + oc * ux * ux;
    float R01 = -ss * uz + oc * ux * uy;
    float R02 =  ss * uy + oc * ux * uz;
    float R10 =  ss * uz + oc * ux * uy;
    float R11 = cc + oc * uy * uy;
    float R12 = -ss * ux + oc * uy * uz;
    float R20 = -ss * uy + oc * ux * uz;
    float R21 =  ss * ux + oc * uy * uz;
    float R22 = cc + oc * uz * uz;

    g_featT[(9*jj+0)*BS + b] = R00 - 1.0f;
    g_featT[(9*jj+1)*BS + b] = R01;
    g_featT[(9*jj+2)*BS + b] = R02;
    g_featT[(9*jj+3)*BS + b] = R10;
    g_featT[(9*jj+4)*BS + b] = R11 - 1.0f;
    g_featT[(9*jj+5)*BS + b] = R12;
    g_featT[(9*jj+6)*BS + b] = R20;
    g_featT[(9*jj+7)*BS + b] = R21;
    g_featT[(9*jj+8)*BS + b] = R22 - 1.0f;
}

// ---------------- kernel 1b: per-(batch,row) SE3 chain ----------------
__global__ void __launch_bounds__(128) k_chain(const float* __restrict__ root_rotation,
                                               const float* __restrict__ shape,
                                               const float* __restrict__ trans,
                                               float* __restrict__ jout) {
    int b = blockIdx.x * 128 + threadIdx.x;
    int r = blockIdx.y;   // 0..2

    float sh[10];
#pragma unroll
    for (int s = 0; s < 10; s++) sh[s] = shape[b * 10 + s];
    if (r == 0) {
#pragma unroll
        for (int s = 0; s < 10; s++) g_featT[(135 + s) * BS + b] = sh[s];
#pragma unroll
        for (int z = 145; z < KPAD; z++) g_featT[z * BS + b] = 0.0f;
    }

    float jt0[3];
#pragma unroll
    for (int d = 0; d < 3; d++) {
        float a = g_JT[d];
        const float* js = g_JS + d * 10;
#pragma unroll
        for (int s = 0; s < 10; s++) a = fmaf(js[s], sh[s], a);
        jt0[d] = a;
    }

    float A[16][4];
    {
        float R0 = root_rotation[b * 9 + r * 3 + 0];
        float R1 = root_rotation[b * 9 + r * 3 + 1];
        float R2 = root_rotation[b * 9 + r * 3 + 2];
        A[0][0] = R0; A[0][1] = R1; A[0][2] = R2;
        A[0][3] = jt0[r] - (R0 * jt0[0] + R1 * jt0[1] + R2 * jt0[2]);
    }

    float center = jt0[r];
    float off = trans[b * 3 + r] - center;
    g_off[r * BS + b] = off;

#pragma unroll
    for (int c = 0; c < 4; c++) g_se3T[(0 * 12 + r * 4 + c) * BS + b] = A[0][c];
    jout[((size_t)b * 21 + 0) * 3 + r] = center + off;

#pragma unroll
    for (int i = 1; i < 16; i++) {
        int p = c_parent[i];
        float jx, jy, jz;
        {
            float a0 = g_JT[i * 3 + 0], a1 = g_JT[i * 3 + 1], a2 = g_JT[i * 3 + 2];
            const float* js0 = g_JS + (i * 3 + 0) * 10;
            const float* js1 = g_JS + (i * 3 + 1) * 10;
            const float* js2 = g_JS + (i * 3 + 2) * 10;
#pragma unroll
            for (int s = 0; s < 10; s++) {
                a0 = fmaf(js0[s], sh[s], a0);
                a1 = fmaf(js1[s], sh[s], a1);
                a2 = fmaf(js2[s], sh[s], a2);
            }
            jx = a0; jy = a1; jz = a2;
        }
        float R[9];
#pragma unroll
        for (int e = 0; e < 9; e++) R[e] = g_featT[(9 * (i - 1) + e) * BS + b];
        R[0] += 1.0f; R[4] += 1.0f; R[8] += 1.0f;

        float t0 = jx - (R[0]*jx + R[1]*jy + R[2]*jz);
        float t1 = jy - (R[3]*jx + R[4]*jy + R[5]*jz);
        float t2 = jz - (R[6]*jx + R[7]*jy + R[8]*jz);

        float p0 = A[p][0], p1 = A[p][1], p2 = A[p][2], p3 = A[p][3];
        A[i][0] = p0*R[0] + p1*R[3] + p2*R[6];
        A[i][1] = p0*R[1] + p1*R[4] + p2*R[7];
        A[i][2] = p0*R[2] + p1*R[5] + p2*R[8];
        A[i][3] = p0*t0 + p1*t1 + p2*t2 + p3;

#pragma unroll
        for (int c = 0; c < 4; c++) g_se3T[(i * 12 + r * 4 + c) * BS + b] = A[i][c];

        float jl = p0*jx + p1*jy + p2*jz + p3;
        jout[((size_t)b * 21 + c_src2pos[i]) * 3 + r] = jl + off;
    }
}

// ---------------- kernel 2: tiled SGEMM (FFMA2): M128 x N128, 8m x 8b micro ----------------
__global__ void __launch_bounds__(256, 2) k_gemm(const float* __restrict__ v_template) {
    __shared__ float As[2][8][256];
    __shared__ float Bs[2][8][128];

    int tid = threadIdx.x;
    int bblk = blockIdx.x * 128;
    int mblk = blockIdx.y * 128;
    int lk  = tid >> 5;
    int l4  = (tid & 31) * 4;

    int tx = tid & 15;
    int ty = tid >> 4;

    ull c[8][4];
#pragma unroll
    for (int m = 0; m < 8; m++)
#pragma unroll
        for (int p = 0; p < 4; p++) c[m][p] = 0ULL;

    F4 a4, b4;
    a4.v = *reinterpret_cast<const float4*>(g_dirsT + lk * MP + mblk + l4);
    b4.v = *reinterpret_cast<const float4*>(g_featT + lk * BS + bblk + l4);
    {
        float4 d0 = make_float4(a4.a[0], a4.a[0], a4.a[1], a4.a[1]);
        float4 d1 = make_float4(a4.a[2], a4.a[2], a4.a[3], a4.a[3]);
        *reinterpret_cast<float4*>(&As[0][lk][2 * l4])     = d0;
        *reinterpret_cast<float4*>(&As[0][lk][2 * l4 + 4]) = d1;
        *reinterpret_cast<float4*>(&Bs[0][lk][l4]) = b4.v;
    }
    __syncthreads();

    for (int s = 0; s < 19; s++) {
        int cur = s & 1;
        bool hasNext = (s + 1 < 19);
        if (hasNext) {
            a4.v = *reinterpret_cast<const float4*>(g_dirsT + ((s+1)*8 + lk) * MP + mblk + l4);
            b4.v = *reinterpret_cast<const float4*>(g_featT + ((s+1)*8 + lk) * BS + bblk + l4);
        }
#pragma unroll
        for (int k = 0; k < 8; k++) {
            U2 a01, a23, a45, a67;
            a01.v = *reinterpret_cast<const ulonglong2*>(&As[cur][k][8 * ty]);
            a23.v = *reinterpret_cast<const ulonglong2*>(&As[cur][k][8 * ty + 4]);
            a45.v = *reinterpret_cast<const ulonglong2*>(&As[cur][k][128 + 8 * ty]);
            a67.v = *reinterpret_cast<const ulonglong2*>(&As[cur][k][128 + 8 * ty + 4]);
            U2 b01, b23;
            b01.v = *reinterpret_cast<const ulonglong2*>(&Bs[cur][k][4 * tx]);
            b23.v = *reinterpret_cast<const ulonglong2*>(&Bs[cur][k][64 + 4 * tx]);
            ull am[8] = {a01.p[0], a01.p[1], a23.p[0], a23.p[1],
                         a45.p[0], a45.p[1], a67.p[0], a67.p[1]};
            ull bn[4] = {b01.p[0], b01.p[1], b23.p[0], b23.p[1]};
#pragma unroll
            for (int m = 0; m < 8; m++)
#pragma unroll
                for (int p = 0; p < 4; p++)
                    c[m][p] = fma2(am[m], bn[p], c[m][p]);
        }
        if (hasNext) {
            int nxt = 1 - cur;
            float4 d0 = make_float4(a4.a[0], a4.a[0], a4.a[1], a4.a[1]);
            float4 d1 = make_float4(a4.a[2], a4.a[2], a4.a[3], a4.a[3]);
            *reinterpret_cast<float4*>(&As[nxt][lk][2 * l4])     = d0;
            *reinterpret_cast<float4*>(&As[nxt][lk][2 * l4 + 4]) = d1;
            *reinterpret_cast<float4*>(&Bs[nxt][lk][l4]) = b4.v;
        }
        __syncthreads();
    }

#pragma unroll
    for (int m = 0; m < 8; m++) {
        int m_local = (m < 4) ? (4 * ty + m) : (64 + 4 * ty + (m - 4));
        int mg = mblk + m_local;
        if (mg >= MROWS) continue;
        float vt = v_template[mg];
        F4 o0, o1;
        unpack2(c[m][0], o0.a[0], o0.a[1]);
        unpack2(c[m][1], o0.a[2], o0.a[3]);
        unpack2(c[m][2], o1.a[0], o1.a[1]);
        unpack2(c[m][3], o1.a[2], o1.a[3]);
#pragma unroll
        for (int i = 0; i < 4; i++) { o0.a[i] += vt; o1.a[i] += vt; }
        *reinterpret_cast<float4*>(g_h + (size_t)mg * BS + bblk + 4 * tx)      = o0.v;
        *reinterpret_cast<float4*>(g_h + (size_t)mg * BS + bblk + 64 + 4 * tx) = o1.v;
    }
}

// ---------------- kernel 3: LBS blend — smem-staged SE3, 4 v x 1 b-pair / thread ----------------
__global__ void __launch_bounds__(256, 2) k_lbs(float* __restrict__ out) {
    __shared__ float sA[VT * SOS];
    __shared__ float sW[16 * VT];

    int tid = threadIdx.x;
    int bx  = tid & 15;
    int vg  = tid >> 4;
    int vblk = blockIdx.x * VT;
    int bblk = blockIdx.y * BT;
    int b0 = bblk + bx * 2;
    int v0 = vblk + vg * 4;

    // A tile [192][BT] = 1536 float4
#pragma unroll
    for (int t = tid; t < 192 * (BT / 4); t += 256) {
        int e = t >> 3;
        int q = (t & 7) * 4;
        *reinterpret_cast<float4*>(&sA[e * BT + q]) =
            *reinterpret_cast<const float4*>(g_se3T + (size_t)e * BS + bblk + q);
    }
    {
        int t = tid;
        int j = t >> 4, q = t & 15;
        *reinterpret_cast<float4*>(&sW[j * VT + q * 4]) =
            *reinterpret_cast<const float4*>(g_wT + j * NVP + vblk + q * 4);
    }

    ull h[4][3];
#pragma unroll
    for (int u = 0; u < 4; u++) {
        int vv = v0 + u;
        if (vv > NV - 1) vv = NV - 1;
#pragma unroll
        for (int d = 0; d < 3; d++) {
            P2 t;
            t.f = *reinterpret_cast<const float2*>(g_h + (size_t)(vv * 3 + d) * BS + b0);
            h[u][d] = t.u;
        }
    }

    __syncthreads();

    ull acc[4][3];
#pragma unroll
    for (int u = 0; u < 4; u++)
#pragma unroll
        for (int r = 0; r < 3; r++) acc[u][r] = 0ULL;

#pragma unroll
    for (int j = 0; j < 16; j++) {
        F4 w4;
        w4.v = *reinterpret_cast<const float4*>(&sW[j * VT + vg * 4]);
        ull A[12];
#pragma unroll
        for (int e = 0; e < 12; e++)
            A[e] = *reinterpret_cast<const ull*>(&sA[(j * 12 + e) * BT + bx * 2]);
#pragma unroll
        for (int u = 0; u < 4; u++) {
            ull wp = pack2(w4.a[u], w4.a[u]);
#pragma unroll
            for (int r = 0; r < 3; r++) {
                ull t = fma2(A[r*4+0], h[u][0],
                        fma2(A[r*4+1], h[u][1],
                        fma2(A[r*4+2], h[u][2], A[r*4+3])));
                acc[u][r] = fma2(wp, t, acc[u][r]);
            }
        }
    }

    ull offp[3];
#pragma unroll
    for (int d = 0; d < 3; d++) {
        P2 t;
        t.f = *reinterpret_cast<const float2*>(g_off + d * BS + b0);
        offp[d] = t.u;
    }

    __syncthreads();
    float* s_out = sA;

#pragma unroll
    for (int u = 0; u < 4; u++) {
        int v = v0 + u;
        bool val = (v < NV);
        int pos = -1;
        if      (v == 745) pos = 4;
        else if (v == 333) pos = 8;
        else if (v == 444) pos = 12;
        else if (v == 555) pos = 16;
        else if (v == 672) pos = 20;
        float o[3][2];
#pragma unroll
        for (int r = 0; r < 3; r++) {
            ull s = add2(acc[u][r], offp[r]);
            unpack2(s, o[r][0], o[r][1]);
        }
        int vl = vg * 4 + u;
#pragma unroll
        for (int i = 0; i < 2; i++) {
            int bl = bx * 2 + i;
            if (val) {
                s_out[vl * SOS + bl * 3 + 0] = o[0][i];
                s_out[vl * SOS + bl * 3 + 1] = o[1][i];
                s_out[vl * SOS + bl * 3 + 2] = o[2][i];
            }
            if (pos >= 0) {
                int b = b0 + i;
                float* jo = out + (size_t)VOUT_ELEMS + ((size_t)b * 21 + pos) * 3;
                jo[0] = o[0][i]; jo[1] = o[1][i]; jo[2] = o[2][i];
            }
        }
    }

    __syncthreads();

    int nv_here = NV - vblk;
    if (nv_here > VT) nv_here = VT;
    int row_floats = nv_here * 3;
#pragma unroll 4
    for (int t = tid; t < BT * (VT * 3); t += 256) {
        int bl = t / (VT * 3);
        int e  = t % (VT * 3);
        if (e < row_floats) {
            int vl = e / 3;
            int d  = e - vl * 3;
            out[((size_t)(bblk + bl) * NV + vblk) * 3 + e] =
                s_out[vl * SOS + bl * 3 + d];
        }
    }
}

// ---------------- launch ----------------
extern "C" void kernel_launch(void* const* d_in, const int* in_sizes, int n_in,
                              void* d_out, int out_size) {
    const float* root_rotation = (const float*)d_in[0];
    const float* pose          = (const float*)d_in[1];
    const float* shape         = (const float*)d_in[2];
    const float* trans         = (const float*)d_in[3];
    const float* hc            = (const float*)d_in[4];
    const float* hm            = (const float*)d_in[5];
    const float* shapedirs     = (const float*)d_in[6];
    const float* posedirs      = (const float*)d_in[7];
    const float* v_template    = (const float*)d_in[8];
    const float* Jreg          = (const float*)d_in[9];
    const float* weights       = (const float*)d_in[10];
    float* out = (float*)d_out;

    k_pre<<<NB_DIRS + NB_W + NB_POSE + NB_JREG, 256>>>(posedirs, shapedirs, weights,
                                                       pose, Jreg, v_template);

    dim3 rgrid(BS / 256, 15);
    k_rot<<<rgrid, 256>>>(hc, hm);
    dim3 cgrid(BS / 128, 3);
    k_chain<<<cgrid, 128>>>(root_rotation, shape, trans, out + VOUT_ELEMS);

    dim3 ggrid(BS / 128, 19);
    k_gemm<<<ggrid, 256>>>(v_template);
    dim3 lgrid((NV + VT - 1) / VT, BS / BT);
    k_lbs<<<lgrid, 256>>>(out);
}

// round 13
// speedup vs baseline: 1.1987x; 1.0500x over previous
#include <cuda_runtime.h>
#include <math.h>

#define BS 4096
#define NV 778
#define KPAD 152                     // K padded to 19*8
#define MROWS 2334                   // NV*3
#define MP 2432                      // M padded to 19*128
#define VOUT_ELEMS (BS * NV * 3)
#define VT 64                        // vertices per lbs block
#define BT 32                        // batches per lbs block
#define NVP 832                      // NV padded to 13*64
#define SOS 97                       // s_out row stride

#define NB_DIRS ((KPAD * MP) / 256)          // 1444
#define NB_W    ((16 * NVP) / 256)           // 52
#define NB_POSE ((45 * BS) / 256)            // 720
#define NB_JREG 48

typedef unsigned long long ull;
union U2 { ulonglong2 v; ull p[2]; };
union F4 { float4 v; float a[4]; };
union P2 { float2 f; ull u; };

__device__ __forceinline__ ull fma2(ull a, ull b, ull c) {
    ull d;
    asm("fma.rn.f32x2 %0, %1, %2, %3;" : "=l"(d) : "l"(a), "l"(b), "l"(c));
    return d;
}
__device__ __forceinline__ ull add2(ull a, ull b) {
    ull d;
    asm("add.rn.f32x2 %0, %1, %2;" : "=l"(d) : "l"(a), "l"(b));
    return d;
}
__device__ __forceinline__ ull pack2(float x, float y) {
    ull d;
    asm("mov.b64 %0, {%1, %2};" : "=l"(d) : "f"(x), "f"(y));
    return d;
}
__device__ __forceinline__ void unpack2(ull p, float& x, float& y) {
    asm("mov.b64 {%0, %1}, %2;" : "=f"(x), "=f"(y) : "l"(p));
}

// ---------------- scratch ----------------
__device__ __align__(16) float g_dirsT[KPAD * MP];    // [k][m]
__device__ __align__(16) float g_featT[KPAD * BS];    // [k][b]
__device__ __align__(16) float g_poseT[45 * BS];      // [c][b]
__device__ __align__(16) float g_h[MROWS * BS];       // [vd][b]
__device__ __align__(16) float g_se3T[192 * BS];      // [e][b]
__device__ __align__(16) float g_off[3 * BS];         // [d][b]
__device__ __align__(16) float g_wT[16 * NVP];        // [j][v]
__device__ float g_JS[16 * 3 * 10];
__device__ float g_JT[16 * 3];

__constant__ int c_parent[16]   = {-1,0,1,2,0,4,5,0,7,8,0,10,11,0,13,14};
__constant__ int c_src2pos[16]  = {0,5,6,7,9,10,11,17,18,19,13,14,15,1,2,3};

// ---------------- kernel 0: merged preprocessing (dirsT | wT | poseT | jreg) ----------------
__global__ void __launch_bounds__(256) k_pre(const float* __restrict__ posedirs,
                                             const float* __restrict__ shapedirs,
                                             const float* __restrict__ weights,
                                             const float* __restrict__ pose,
                                             const float* __restrict__ Jreg,
                                             const float* __restrict__ v_template) {
    __shared__ float red[256][11];
    int jb = blockIdx.x;
    int tid = threadIdx.x;

    if (jb < NB_DIRS) {
        int idx = jb * 256 + tid;
        int m = idx % MP;
        int k = idx / MP;
        float val = 0.0f;
        if (m < MROWS) {
            if (k < 135)      val = posedirs[m * 135 + k];
            else if (k < 145) val = shapedirs[m * 10 + (k - 135)];
        }
        g_dirsT[idx] = val;
        return;
    }
    jb -= NB_DIRS;
    if (jb < NB_W) {
        int idx = jb * 256 + tid;
        int v = idx % NVP;
        int j = idx / NVP;
        g_wT[idx] = (v < NV) ? weights[v * 16 + j] : 0.0f;
        return;
    }
    jb -= NB_W;
    if (jb < NB_POSE) {
        int idx = jb * 256 + tid;
        int b = idx % BS;
        int c = idx / BS;
        g_poseT[idx] = pose[b * 45 + c];
        return;
    }
    jb -= NB_POSE;
    {
        int jd = jb;                 // 0..47
        int j = jd / 3, d = jd % 3;
        float acc[11];
#pragma unroll
        for (int i = 0; i < 11; i++) acc[i] = 0.0f;
        for (int v = tid; v < NV; v += 256) {
            float r = Jreg[j * NV + v];
            const float* sd = shapedirs + (v * 3 + d) * 10;
#pragma unroll
            for (int s = 0; s < 10; s++) acc[s] = fmaf(r, sd[s], acc[s]);
            acc[10] = fmaf(r, v_template[v * 3 + d], acc[10]);
        }
#pragma unroll
        for (int i = 0; i < 11; i++) red[tid][i] = acc[i];
        __syncthreads();
        for (int off = 128; off > 0; off >>= 1) {
            if (tid < off) {
#pragma unroll
                for (int i = 0; i < 11; i++) red[tid][i] += red[tid + off][i];
            }
            __syncthreads();
        }
        if (tid == 0) {
#pragma unroll
            for (int s = 0; s < 10; s++) g_JS[jd * 10 + s] = red[0][s];
            g_JT[jd] = red[0][10];
        }
    }
}

// ---------------- kernel 1a: per-(batch,joint) Rodrigues ----------------
__global__ void __launch_bounds__(256) k_rot(const float* __restrict__ hc,
                                             const float* __restrict__ hm) {
    int b  = blockIdx.x * 256 + threadIdx.x;
    int jj = blockIdx.y;   // 0..14

    float ax = hm[3 * jj], ay = hm[3 * jj + 1], az = hm[3 * jj + 2];
    for (int c = 0; c < 45; c++) {
        float p = g_poseT[c * BS + b];
        const float* h = hc + c * 45 + 3 * jj;
        ax = fmaf(p, h[0], ax);
        ay = fmaf(p, h[1], ay);
        az = fmaf(p, h[2], az);
    }
    float a2  = ax * ax + ay * ay + az * az + 1e-12f;
    float ang = sqrtf(a2);
    float inv = 1.0f / ang;
    float ux = ax * inv, uy = ay * inv, uz = az * inv;
    float cc = cosf(ang), ss = sinf(ang), oc = 1.0f - cc;
    float R00 = cc + oc * ux * ux;
    float R01 = -ss * uz + oc * ux * uy;
    float R02 =  ss * uy + oc * ux * uz;
    float R10 =  ss * uz + oc * ux * uy;
    float R11 = cc + oc * uy * uy;
    float R12 = -ss * ux + oc * uy * uz;
    float R20 = -ss * uy + oc * ux * uz;
    float R21 =  ss * ux + oc * uy * uz;
    float R22 = cc + oc * uz * uz;

    g_featT[(9*jj+0)*BS + b] = R00 - 1.0f;
    g_featT[(9*jj+1)*BS + b] = R01;
    g_featT[(9*jj+2)*BS + b] = R02;
    g_featT[(9*jj+3)*BS + b] = R10;
    g_featT[(9*jj+4)*BS + b] = R11 - 1.0f;
    g_featT[(9*jj+5)*BS + b] = R12;
    g_featT[(9*jj+6)*BS + b] = R20;
    g_featT[(9*jj+7)*BS + b] = R21;
    g_featT[(9*jj+8)*BS + b] = R22 - 1.0f;
}

// ---------------- kernel 1b: per-(batch,row) SE3 chain ----------------
__global__ void __launch_bounds__(128) k_chain(const float* __restrict__ root_rotation,
                                               const float* __restrict__ shape,
                                               const float* __restrict__ trans,
                                               float* __restrict__ jout) {
    int b = blockIdx.x * 128 + threadIdx.x;
    int r = blockIdx.y;   // 0..2

    float sh[10];
#pragma unroll
    for (int s = 0; s < 10; s++) sh[s] = shape[b * 10 + s];
    if (r == 0) {
#pragma unroll
        for (int s = 0; s < 10; s++) g_featT[(135 + s) * BS + b] = sh[s];
#pragma unroll
        for (int z = 145; z < KPAD; z++) g_featT[z * BS + b] = 0.0f;
    }

    float jt0[3];
#pragma unroll
    for (int d = 0; d < 3; d++) {
        float a = g_JT[d];
        const float* js = g_JS + d * 10;
#pragma unroll
        for (int s = 0; s < 10; s++) a = fmaf(js[s], sh[s], a);
        jt0[d] = a;
    }

    float A[16][4];
    {
        float R0 = root_rotation[b * 9 + r * 3 + 0];
        float R1 = root_rotation[b * 9 + r * 3 + 1];
        float R2 = root_rotation[b * 9 + r * 3 + 2];
        A[0][0] = R0; A[0][1] = R1; A[0][2] = R2;
        A[0][3] = jt0[r] - (R0 * jt0[0] + R1 * jt0[1] + R2 * jt0[2]);
    }

    float center = jt0[r];
    float off = trans[b * 3 + r] - center;
    g_off[r * BS + b] = off;

#pragma unroll
    for (int c = 0; c < 4; c++) g_se3T[(0 * 12 + r * 4 + c) * BS + b] = A[0][c];
    jout[((size_t)b * 21 + 0) * 3 + r] = center + off;

#pragma unroll
    for (int i = 1; i < 16; i++) {
        int p = c_parent[i];
        float jx, jy, jz;
        {
            float a0 = g_JT[i * 3 + 0], a1 = g_JT[i * 3 + 1], a2 = g_JT[i * 3 + 2];
            const float* js0 = g_JS + (i * 3 + 0) * 10;
            const float* js1 = g_JS + (i * 3 + 1) * 10;
            const float* js2 = g_JS + (i * 3 + 2) * 10;
#pragma unroll
            for (int s = 0; s < 10; s++) {
                a0 = fmaf(js0[s], sh[s], a0);
                a1 = fmaf(js1[s], sh[s], a1);
                a2 = fmaf(js2[s], sh[s], a2);
            }
            jx = a0; jy = a1; jz = a2;
        }
        float R[9];
#pragma unroll
        for (int e = 0; e < 9; e++) R[e] = g_featT[(9 * (i - 1) + e) * BS + b];
        R[0] += 1.0f; R[4] += 1.0f; R[8] += 1.0f;

        float t0 = jx - (R[0]*jx + R[1]*jy + R[2]*jz);
        float t1 = jy - (R[3]*jx + R[4]*jy + R[5]*jz);
        float t2 = jz - (R[6]*jx + R[7]*jy + R[8]*jz);

        float p0 = A[p][0], p1 = A[p][1], p2 = A[p][2], p3 = A[p][3];
        A[i][0] = p0*R[0] + p1*R[3] + p2*R[6];
        A[i][1] = p0*R[1] + p1*R[4] + p2*R[7];
        A[i][2] = p0*R[2] + p1*R[5] + p2*R[8];
        A[i][3] = p0*t0 + p1*t1 + p2*t2 + p3;

#pragma unroll
        for (int c = 0; c < 4; c++) g_se3T[(i * 12 + r * 4 + c) * BS + b] = A[i][c];

        float jl = p0*jx + p1*jy + p2*jz + p3;
        jout[((size_t)b * 21 + c_src2pos[i]) * 3 + r] = jl + off;
    }
}

// ---------------- kernel 2: tiled SGEMM (FFMA2), A de-duplicated in smem ----------------
__global__ void __launch_bounds__(256, 2) k_gemm(const float* __restrict__ v_template) {
    __shared__ float As[2][8][128];   // plain m values (no duplication)
    __shared__ float Bs[2][8][128];

    int tid = threadIdx.x;
    int bblk = blockIdx.x * 128;
    int mblk = blockIdx.y * 128;
    int lk  = tid >> 5;
    int l4  = (tid & 31) * 4;

    int tx = tid & 15;
    int ty = tid >> 4;

    ull c[8][4];
#pragma unroll
    for (int m = 0; m < 8; m++)
#pragma unroll
        for (int p = 0; p < 4; p++) c[m][p] = 0ULL;

    F4 a4, b4;
    a4.v = *reinterpret_cast<const float4*>(g_dirsT + lk * MP + mblk + l4);
    b4.v = *reinterpret_cast<const float4*>(g_featT + lk * BS + bblk + l4);
    {
        *reinterpret_cast<float4*>(&As[0][lk][l4]) = a4.v;
        *reinterpret_cast<float4*>(&Bs[0][lk][l4]) = b4.v;
    }
    __syncthreads();

    for (int s = 0; s < 19; s++) {
        int cur = s & 1;
        bool hasNext = (s + 1 < 19);
        if (hasNext) {
            a4.v = *reinterpret_cast<const float4*>(g_dirsT + ((s+1)*8 + lk) * MP + mblk + l4);
            b4.v = *reinterpret_cast<const float4*>(g_featT + ((s+1)*8 + lk) * BS + bblk + l4);
        }
#pragma unroll
        for (int k = 0; k < 8; k++) {
            F4 a03, a47;
            a03.v = *reinterpret_cast<const float4*>(&As[cur][k][4 * ty]);
            a47.v = *reinterpret_cast<const float4*>(&As[cur][k][64 + 4 * ty]);
            U2 b01, b23;
            b01.v = *reinterpret_cast<const ulonglong2*>(&Bs[cur][k][4 * tx]);
            b23.v = *reinterpret_cast<const ulonglong2*>(&Bs[cur][k][64 + 4 * tx]);
#pragma unroll
            for (int m = 0; m < 8; m++) {
                float av = (m < 4) ? a03.a[m] : a47.a[m - 4];
                ull amp = pack2(av, av);
                c[m][0] = fma2(amp, b01.p[0], c[m][0]);
                c[m][1] = fma2(amp, b01.p[1], c[m][1]);
                c[m][2] = fma2(amp, b23.p[0], c[m][2]);
                c[m][3] = fma2(amp, b23.p[1], c[m][3]);
            }
        }
        if (hasNext) {
            int nxt = 1 - cur;
            *reinterpret_cast<float4*>(&As[nxt][lk][l4]) = a4.v;
            *reinterpret_cast<float4*>(&Bs[nxt][lk][l4]) = b4.v;
        }
        __syncthreads();
    }

#pragma unroll
    for (int m = 0; m < 8; m++) {
        int m_local = (m < 4) ? (4 * ty + m) : (64 + 4 * ty + (m - 4));
        int mg = mblk + m_local;
        if (mg >= MROWS) continue;
        float vt = v_template[mg];
        F4 o0, o1;
        unpack2(c[m][0], o0.a[0], o0.a[1]);
        unpack2(c[m][1], o0.a[2], o0.a[3]);
        unpack2(c[m][2], o1.a[0], o1.a[1]);
        unpack2(c[m][3], o1.a[2], o1.a[3]);
#pragma unroll
        for (int i = 0; i < 4; i++) { o0.a[i] += vt; o1.a[i] += vt; }
        *reinterpret_cast<float4*>(g_h + (size_t)mg * BS + bblk + 4 * tx)      = o0.v;
        *reinterpret_cast<float4*>(g_h + (size_t)mg * BS + bblk + 64 + 4 * tx) = o1.v;
    }
}

// ---------------- kernel 3: LBS blend — smem-staged SE3, 4 v x 1 b-pair / thread ----------------
__global__ void __launch_bounds__(256, 2) k_lbs(float* __restrict__ out) {
    __shared__ float sA[VT * SOS];
    __shared__ float sW[16 * VT];

    int tid = threadIdx.x;
    int bx  = tid & 15;
    int vg  = tid >> 4;
    int vblk = blockIdx.x * VT;
    int bblk = blockIdx.y * BT;
    int b0 = bblk + bx * 2;
    int v0 = vblk + vg * 4;

    // A tile [192][BT] = 1536 float4
#pragma unroll
    for (int t = tid; t < 192 * (BT / 4); t += 256) {
        int e = t >> 3;
        int q = (t & 7) * 4;
        *reinterpret_cast<float4*>(&sA[e * BT + q]) =
            *reinterpret_cast<const float4*>(g_se3T + (size_t)e * BS + bblk + q);
    }
    {
        int t = tid;
        int j = t >> 4, q = t & 15;
        *reinterpret_cast<float4*>(&sW[j * VT + q * 4]) =
            *reinterpret_cast<const float4*>(g_wT + j * NVP + vblk + q * 4);
    }

    ull h[4][3];
#pragma unroll
    for (int u = 0; u < 4; u++) {
        int vv = v0 + u;
        if (vv > NV - 1) vv = NV - 1;
#pragma unroll
        for (int d = 0; d < 3; d++) {
            P2 t;
            t.f = *reinterpret_cast<const float2*>(g_h + (size_t)(vv * 3 + d) * BS + b0);
            h[u][d] = t.u;
        }
    }

    __syncthreads();

    ull acc[4][3];
#pragma unroll
    for (int u = 0; u < 4; u++)
#pragma unroll
        for (int r = 0; r < 3; r++) acc[u][r] = 0ULL;

#pragma unroll
    for (int j = 0; j < 16; j++) {
        F4 w4;
        w4.v = *reinterpret_cast<const float4*>(&sW[j * VT + vg * 4]);
        ull A[12];
#pragma unroll
        for (int e = 0; e < 12; e++)
            A[e] = *reinterpret_cast<const ull*>(&sA[(j * 12 + e) * BT + bx * 2]);
#pragma unroll
        for (int u = 0; u < 4; u++) {
            ull wp = pack2(w4.a[u], w4.a[u]);
#pragma unroll
            for (int r = 0; r < 3; r++) {
                ull t = fma2(A[r*4+0], h[u][0],
                        fma2(A[r*4+1], h[u][1],
                        fma2(A[r*4+2], h[u][2], A[r*4+3])));
                acc[u][r] = fma2(wp, t, acc[u][r]);
            }
        }
    }

    ull offp[3];
#pragma unroll
    for (int d = 0; d < 3; d++) {
        P2 t;
        t.f = *reinterpret_cast<const float2*>(g_off + d * BS + b0);
        offp[d] = t.u;
    }

    __syncthreads();
    float* s_out = sA;

#pragma unroll
    for (int u = 0; u < 4; u++) {
        int v = v0 + u;
        bool val = (v < NV);
        int pos = -1;
        if      (v == 745) pos = 4;
        else if (v == 333) pos = 8;
        else if (v == 444) pos = 12;
        else if (v == 555) pos = 16;
        else if (v == 672) pos = 20;
        float o[3][2];
#pragma unroll
        for (int r = 0; r < 3; r++) {
            ull s = add2(acc[u][r], offp[r]);
            unpack2(s, o[r][0], o[r][1]);
        }
        int vl = vg * 4 + u;
#pragma unroll
        for (int i = 0; i < 2; i++) {
            int bl = bx * 2 + i;
            if (val) {
                s_out[vl * SOS + bl * 3 + 0] = o[0][i];
                s_out[vl * SOS + bl * 3 + 1] = o[1][i];
                s_out[vl * SOS + bl * 3 + 2] = o[2][i];
            }
            if (pos >= 0) {
                int b = b0 + i;
                float* jo = out + (size_t)VOUT_ELEMS + ((size_t)b * 21 + pos) * 3;
                jo[0] = o[0][i]; jo[1] = o[1][i]; jo[2] = o[2][i];
            }
        }
    }

    __syncthreads();

    int nv_here = NV - vblk;
    if (nv_here > VT) nv_here = VT;
    int row_floats = nv_here * 3;
#pragma unroll 4
    for (int t = tid; t < BT * (VT * 3); t += 256) {
        int bl = t / (VT * 3);
        int e  = t % (VT * 3);
        if (e < row_floats) {
            int vl = e / 3;
            int d  = e - vl * 3;
            out[((size_t)(bblk + bl) * NV + vblk) * 3 + e] =
                s_out[vl * SOS + bl * 3 + d];
        }
    }
}

// ---------------- launch ----------------
extern "C" void kernel_launch(void* const* d_in, const int* in_sizes, int n_in,
                              void* d_out, int out_size) {
    const float* root_rotation = (const float*)d_in[0];
    const float* pose          = (const float*)d_in[1];
    const float* shape         = (const float*)d_in[2];
    const float* trans         = (const float*)d_in[3];
    const float* hc            = (const float*)d_in[4];
    const float* hm            = (const float*)d_in[5];
    const float* shapedirs     = (const float*)d_in[6];
    const float* posedirs      = (const float*)d_in[7];
    const float* v_template    = (const float*)d_in[8];
    const float* Jreg          = (const float*)d_in[9];
    const float* weights       = (const float*)d_in[10];
    float* out = (float*)d_out;

    k_pre<<<NB_DIRS + NB_W + NB_POSE + NB_JREG, 256>>>(posedirs, shapedirs, weights,
                                                       pose, Jreg, v_template);

    dim3 rgrid(BS / 256, 15);
    k_rot<<<rgrid, 256>>>(hc, hm);
    dim3 cgrid(BS / 128, 3);
    k_chain<<<cgrid, 128>>>(root_rotation, shape, trans, out + VOUT_ELEMS);

    dim3 ggrid(BS / 128, 19);
    k_gemm<<<ggrid, 256>>>(v_template);
    dim3 lgrid((NV + VT - 1) / VT, BS / BT);
    k_lbs<<<lgrid, 256>>>(out);
}